// round 1
// baseline (speedup 1.0000x reference)
#include <cuda_runtime.h>
#include <math.h>

// Shapes (fixed for this problem)
#define B_  16
#define S_  512
#define E_  128
#define T_  640      // S_ + E_
#define D_  768
#define H_  12
#define DH_ 64
#define FF_ 3072
#define NT_ (B_*T_) // 10240

// ---------------- scratch (__device__ globals: the allowed scratch path) ----
__device__ float g_q1 [(size_t)NT_*D_];   // word rows: q_ww, entity rows: q_ew
__device__ float g_q2 [(size_t)NT_*D_];   // word rows: q_we, entity rows: q_ee
__device__ float g_k  [(size_t)NT_*D_];
__device__ float g_v  [(size_t)NT_*D_];
__device__ float g_ctx[(size_t)NT_*D_];
__device__ float g_ao [(size_t)NT_*D_];
__device__ float g_tmp[(size_t)NT_*D_];
__device__ float g_inter[(size_t)NT_*FF_];

// ---------------- GEMM: Y[m,n] = X[m,:] @ W[:,n] + bias[n] --------------------
// Output rows are remapped: phys_row = (m/seg)*T_ + (m%seg) + rowoff
// (seg=S_/E_ interleaves word/entity slices into [B,T,D]; seg=M => identity).
// Requires M%128==0, N%128==0, K%16==0 (all shapes here satisfy this).
__global__ __launch_bounds__(256)
void gemm_bias(const float* __restrict__ X, const float* __restrict__ W,
               const float* __restrict__ bias, float* __restrict__ Y,
               int M, int N, int K, int seg, int rowoff)
{
    __shared__ float As[16][128];   // transposed A tile: As[k][m]
    __shared__ float Bs[16][128];   // Bs[k][n]
    const int tid = threadIdx.x;
    const int tx = tid & 15;        // 16 cols of micro-tiles
    const int ty = tid >> 4;        // 16 rows of micro-tiles
    const int n0 = blockIdx.x * 128;
    const int m0 = blockIdx.y * 128;

    float acc[8][8];
#pragma unroll
    for (int i = 0; i < 8; i++)
#pragma unroll
        for (int j = 0; j < 8; j++) acc[i][j] = 0.f;

    for (int k0 = 0; k0 < K; k0 += 16) {
        // A tile: 128 rows x 16 k, loaded as float4 along K, stored transposed
#pragma unroll
        for (int it = 0; it < 2; it++) {
            int f   = tid * 2 + it;          // 0..511
            int ar  = f >> 2;                // 0..127
            int ac4 = (f & 3) * 4;           // 0,4,8,12
            float4 av = *(const float4*)(X + (size_t)(m0 + ar) * K + k0 + ac4);
            As[ac4 + 0][ar] = av.x;
            As[ac4 + 1][ar] = av.y;
            As[ac4 + 2][ar] = av.z;
            As[ac4 + 3][ar] = av.w;
        }
        // B tile: 16 k x 128 n, coalesced float4
#pragma unroll
        for (int it = 0; it < 2; it++) {
            int f   = tid * 2 + it;          // 0..511
            int br  = f >> 5;                // 0..15
            int bc4 = (f & 31) * 4;          // 0..124
            *(float4*)&Bs[br][bc4] =
                *(const float4*)(W + (size_t)(k0 + br) * N + n0 + bc4);
        }
        __syncthreads();
#pragma unroll
        for (int kk = 0; kk < 16; kk++) {
            float a[8], b[8];
            *(float4*)&a[0] = *(const float4*)&As[kk][ty * 8];
            *(float4*)&a[4] = *(const float4*)&As[kk][ty * 8 + 4];
            *(float4*)&b[0] = *(const float4*)&Bs[kk][tx * 8];
            *(float4*)&b[4] = *(const float4*)&Bs[kk][tx * 8 + 4];
#pragma unroll
            for (int i = 0; i < 8; i++)
#pragma unroll
                for (int j = 0; j < 8; j++) acc[i][j] += a[i] * b[j];
        }
        __syncthreads();
    }

    float bv[8];
#pragma unroll
    for (int j = 0; j < 8; j++) bv[j] = bias[n0 + tx * 8 + j];

#pragma unroll
    for (int i = 0; i < 8; i++) {
        int mlog = m0 + ty * 8 + i;
        size_t phys = (size_t)(mlog / seg) * T_ + (mlog % seg) + rowoff;
        float* yr = Y + phys * (size_t)N + n0 + tx * 8;
        float o[8];
#pragma unroll
        for (int j = 0; j < 8; j++) o[j] = acc[i][j] + bv[j];
        *(float4*)yr       = *(float4*)&o[0];
        *(float4*)(yr + 4) = *(float4*)&o[4];
    }
}

// ---------------- attention ------------------------------------------------
// One block = (b, h, 8 query rows). Full 640-wide score row kept in smem.
// Key tiles of 64: since S_=512 is a multiple of 64, each key tile is purely
// word-keys or purely entity-keys -> per-tile q1s/q2s pointer select.
__global__ __launch_bounds__(256)
void attn_kernel(const float* __restrict__ q1, const float* __restrict__ q2,
                 const float* __restrict__ k,  const float* __restrict__ v,
                 const float* __restrict__ mask, float* __restrict__ ctx)
{
    __shared__ float sc [8][T_];      // 20480 B
    __shared__ float q1s[8][DH_];     //  2048 B
    __shared__ float q2s[8][DH_];     //  2048 B
    __shared__ float kts[DH_][65];    // 16640 B (transposed K tile / V tile)

    const int b  = blockIdx.z;
    const int h  = blockIdx.y;
    const int q0 = blockIdx.x * 8;
    const int tid = threadIdx.x;
    const size_t base = ((size_t)b * T_) * D_ + (size_t)h * DH_;

    for (int f = tid; f < 8 * DH_; f += 256) {
        int qi = f >> 6, d = f & 63;
        q1s[qi][d] = q1[base + (size_t)(q0 + qi) * D_ + d];
        q2s[qi][d] = q2[base + (size_t)(q0 + qi) * D_ + d];
    }

    const int qi   = tid >> 5;   // 0..7
    const int lane = tid & 31;

    // scores
    for (int kt0 = 0; kt0 < T_; kt0 += 64) {
        __syncthreads();
        for (int f = tid; f < 64 * DH_; f += 256) {
            int tr = f >> 6, d = f & 63;
            kts[d][tr] = k[base + (size_t)(kt0 + tr) * D_ + d];  // transpose
        }
        __syncthreads();
        const float (*qs)[DH_] = (kt0 < S_) ? q1s : q2s;
        float a0 = 0.f, a1 = 0.f;
#pragma unroll 8
        for (int d = 0; d < DH_; d++) {
            float qv = qs[qi][d];
            a0 += qv * kts[d][lane];
            a1 += qv * kts[d][lane + 32];
        }
        sc[qi][kt0 + lane]      = a0 * 0.125f + mask[b * T_ + kt0 + lane];
        sc[qi][kt0 + lane + 32] = a1 * 0.125f + mask[b * T_ + kt0 + lane + 32];
    }
    __syncthreads();

    // softmax: one warp per query row
    {
        const int w = tid >> 5;
        float mx = -3.4e38f;
        for (int t = lane; t < T_; t += 32) mx = fmaxf(mx, sc[w][t]);
#pragma unroll
        for (int o = 16; o; o >>= 1) mx = fmaxf(mx, __shfl_xor_sync(0xffffffffu, mx, o));
        float sum = 0.f;
        for (int t = lane; t < T_; t += 32) {
            float e = expf(sc[w][t] - mx);
            sc[w][t] = e;
            sum += e;
        }
#pragma unroll
        for (int o = 16; o; o >>= 1) sum += __shfl_xor_sync(0xffffffffu, sum, o);
        float inv = 1.f / sum;
        for (int t = lane; t < T_; t += 32) sc[w][t] *= inv;
    }

    // probs @ V
    float c0 = 0.f, c1 = 0.f;
    for (int vt0 = 0; vt0 < T_; vt0 += 64) {
        __syncthreads();
        for (int f = tid; f < 64 * DH_; f += 256) {
            int tr = f >> 6, d = f & 63;
            kts[tr][d] = v[base + (size_t)(vt0 + tr) * D_ + d];  // non-transposed
        }
        __syncthreads();
#pragma unroll 8
        for (int t = 0; t < 64; t++) {
            float p = sc[qi][vt0 + t];
            c0 += p * kts[t][lane];
            c1 += p * kts[t][lane + 32];
        }
    }
    ctx[base + (size_t)(q0 + qi) * D_ + lane]      = c0;
    ctx[base + (size_t)(q0 + qi) * D_ + lane + 32] = c1;
}

// ---------------- residual + LayerNorm -------------------------------------
// raw already contains (X@W + bias). Adds residual, LayerNorm (eps=1e-12).
// use_full=1 -> residual from rfull (contiguous [NT,D]); else from word/entity
// inputs. final_mode=1 -> write split (word block, then entity block) layout.
__global__ __launch_bounds__(256)
void ln_kernel(const float* __restrict__ raw,
               const float* __restrict__ rw, const float* __restrict__ re,
               const float* __restrict__ rfull, int use_full,
               const float* __restrict__ gm, const float* __restrict__ bt,
               float* __restrict__ out, int final_mode)
{
    const int row = blockIdx.x;
    const int b = row / T_, t = row % T_;
    const float* rp = use_full
        ? rfull + (size_t)row * D_
        : (t < S_ ? rw + ((size_t)(b * S_ + t)) * D_
                  : re + ((size_t)(b * E_ + t - S_)) * D_);
    const float* x = raw + (size_t)row * D_;

    float vv[3];
    float s = 0.f, sq = 0.f;
#pragma unroll
    for (int i = 0; i < 3; i++) {
        int c = threadIdx.x + i * 256;
        float val = x[c] + rp[c];
        vv[i] = val;
        s += val;
        sq += val * val;
    }
    const int lane = threadIdx.x & 31, w = threadIdx.x >> 5;
#pragma unroll
    for (int o = 16; o; o >>= 1) {
        s  += __shfl_xor_sync(0xffffffffu, s,  o);
        sq += __shfl_xor_sync(0xffffffffu, sq, o);
    }
    __shared__ float ws[8], wq[8];
    __shared__ float sm, sv;
    if (lane == 0) { ws[w] = s; wq[w] = sq; }
    __syncthreads();
    if (threadIdx.x == 0) {
        float ts = 0.f, tq = 0.f;
#pragma unroll
        for (int i = 0; i < 8; i++) { ts += ws[i]; tq += wq[i]; }
        float mean = ts * (1.f / D_);
        sm = mean;
        sv = rsqrtf(tq * (1.f / D_) - mean * mean + 1e-12f);
    }
    __syncthreads();
    const float mean = sm, inv = sv;

    float* o = final_mode
        ? (t < S_ ? out + ((size_t)(b * S_ + t)) * D_
                  : out + (size_t)B_ * S_ * D_ + ((size_t)(b * E_ + t - S_)) * D_)
        : out + (size_t)row * D_;
#pragma unroll
    for (int i = 0; i < 3; i++) {
        int c = threadIdx.x + i * 256;
        o[c] = (vv[i] - mean) * inv * gm[c] + bt[c];
    }
}

// ---------------- exact GELU (erf-based) ------------------------------------
__global__ __launch_bounds__(256)
void gelu_kernel(float* __restrict__ x)
{
    size_t i = (size_t)blockIdx.x * 256 + threadIdx.x;  // float4 index
    float4* p = ((float4*)x) + i;
    float4 v = *p;
    v.x = v.x * normcdff(v.x);
    v.y = v.y * normcdff(v.y);
    v.z = v.z * normcdff(v.z);
    v.w = v.w * normcdff(v.w);
    *p = v;
}

// ---------------- host -------------------------------------------------------
extern "C" void kernel_launch(void* const* d_in, const int* in_sizes, int n_in,
                              void* d_out, int out_size)
{
    const float* word  = (const float*)d_in[0];
    const float* ent   = (const float*)d_in[1];
    const float* mask  = (const float*)d_in[2];
    const float* W_q   = (const float*)d_in[3],  *b_q    = (const float*)d_in[4];
    const float* W_k   = (const float*)d_in[5],  *b_k    = (const float*)d_in[6];
    const float* W_v   = (const float*)d_in[7],  *b_v    = (const float*)d_in[8];
    const float* W_w2e = (const float*)d_in[9],  *b_w2e  = (const float*)d_in[10];
    const float* W_e2w = (const float*)d_in[11], *b_e2w  = (const float*)d_in[12];
    const float* W_e2e = (const float*)d_in[13], *b_e2e  = (const float*)d_in[14];
    const float* W_ao  = (const float*)d_in[15], *b_ao   = (const float*)d_in[16];
    const float* gm_ao = (const float*)d_in[17], *bt_ao  = (const float*)d_in[18];
    const float* W_i   = (const float*)d_in[19], *b_i    = (const float*)d_in[20];
    const float* W_o   = (const float*)d_in[21], *b_o    = (const float*)d_in[22];
    const float* gm_o  = (const float*)d_in[23], *bt_o   = (const float*)d_in[24];

    void* p;
    cudaGetSymbolAddress(&p, g_q1);    float* d_q1    = (float*)p;
    cudaGetSymbolAddress(&p, g_q2);    float* d_q2    = (float*)p;
    cudaGetSymbolAddress(&p, g_k);     float* d_k     = (float*)p;
    cudaGetSymbolAddress(&p, g_v);     float* d_v     = (float*)p;
    cudaGetSymbolAddress(&p, g_ctx);   float* d_ctx   = (float*)p;
    cudaGetSymbolAddress(&p, g_ao);    float* d_ao    = (float*)p;
    cudaGetSymbolAddress(&p, g_tmp);   float* d_tmp   = (float*)p;
    cudaGetSymbolAddress(&p, g_inter); float* d_inter = (float*)p;

    const dim3 thr(256);
    const int MW = B_ * S_;   // 8192 word rows
    const int ME = B_ * E_;   // 2048 entity rows

    // Projections (interleaved straight into [B, T, D] buffers)
    gemm_bias<<<dim3(D_/128, MW/128), thr>>>(word, W_q,   b_q,   d_q1, MW, D_, D_, S_, 0);
    gemm_bias<<<dim3(D_/128, MW/128), thr>>>(word, W_w2e, b_w2e, d_q2, MW, D_, D_, S_, 0);
    gemm_bias<<<dim3(D_/128, ME/128), thr>>>(ent,  W_e2w, b_e2w, d_q1, ME, D_, D_, E_, S_);
    gemm_bias<<<dim3(D_/128, ME/128), thr>>>(ent,  W_e2e, b_e2e, d_q2, ME, D_, D_, E_, S_);
    gemm_bias<<<dim3(D_/128, MW/128), thr>>>(word, W_k,   b_k,   d_k,  MW, D_, D_, S_, 0);
    gemm_bias<<<dim3(D_/128, ME/128), thr>>>(ent,  W_k,   b_k,   d_k,  ME, D_, D_, E_, S_);
    gemm_bias<<<dim3(D_/128, MW/128), thr>>>(word, W_v,   b_v,   d_v,  MW, D_, D_, S_, 0);
    gemm_bias<<<dim3(D_/128, ME/128), thr>>>(ent,  W_v,   b_v,   d_v,  ME, D_, D_, E_, S_);

    // Attention
    attn_kernel<<<dim3(T_/8, H_, B_), thr>>>(d_q1, d_q2, d_k, d_v, mask, d_ctx);

    // ctx @ W_ao + b_ao -> tmp ; LN(tmp + kv_in) -> ao
    gemm_bias<<<dim3(D_/128, NT_/128), thr>>>(d_ctx, W_ao, b_ao, d_tmp, NT_, D_, D_, NT_, 0);
    ln_kernel<<<NT_, thr>>>(d_tmp, word, ent, d_ao, /*use_full=*/0, gm_ao, bt_ao, d_ao, /*final=*/0);

    // FFN
    gemm_bias<<<dim3(FF_/128, NT_/128), thr>>>(d_ao, W_i, b_i, d_inter, NT_, FF_, D_, NT_, 0);
    gelu_kernel<<<(unsigned)((size_t)NT_ * FF_ / 1024), thr>>>(d_inter);
    gemm_bias<<<dim3(D_/128, NT_/128), thr>>>(d_inter, W_o, b_o, d_tmp, NT_, D_, FF_, NT_, 0);

    // LN(tmp + ao) -> split (word, entity) output layout
    ln_kernel<<<NT_, thr>>>(d_tmp, nullptr, nullptr, d_ao, /*use_full=*/1, gm_o, bt_o,
                            (float*)d_out, /*final=*/1);
}

// round 4
// speedup vs baseline: 1.5603x; 1.5603x over previous
#include <cuda_runtime.h>
#include <cuda_bf16.h>
#include <stdint.h>
#include <math.h>

// Shapes (fixed for this problem)
#define B_  16
#define S_  512
#define E_  128
#define T_  640      // S_ + E_
#define D_  768
#define H_  12
#define DH_ 64
#define FF_ 3072
#define NT_ (B_*T_) // 10240

typedef __nv_bfloat16 bf16;
typedef unsigned int       u32;
typedef unsigned long long u64;

// ---------------- scratch (__device__ globals) ------------------------------
__device__ float g_q1 [(size_t)NT_*D_];
__device__ float g_q2 [(size_t)NT_*D_];
__device__ float g_k  [(size_t)NT_*D_];
__device__ float g_v  [(size_t)NT_*D_];
__device__ float g_ctx[(size_t)NT_*D_];
__device__ float g_ao [(size_t)NT_*D_];
__device__ float g_tmp[(size_t)NT_*D_];

// bf16 split activations
__device__ bf16 g_word_h[(size_t)B_*S_*D_], g_word_l[(size_t)B_*S_*D_];
__device__ bf16 g_ent_h [(size_t)B_*E_*D_], g_ent_l [(size_t)B_*E_*D_];
__device__ bf16 g_ctx_h [(size_t)NT_*D_],   g_ctx_l [(size_t)NT_*D_];
__device__ bf16 g_ao_h  [(size_t)NT_*D_],   g_ao_l  [(size_t)NT_*D_];
__device__ bf16 g_int_h [(size_t)NT_*FF_],  g_int_l [(size_t)NT_*FF_];

// bf16 split transposed weights (stored as [N, K] row-major)
__device__ bf16 g_wq_h [D_*D_], g_wq_l [D_*D_];
__device__ bf16 g_wk_h [D_*D_], g_wk_l [D_*D_];
__device__ bf16 g_wv_h [D_*D_], g_wv_l [D_*D_];
__device__ bf16 g_w2e_h[D_*D_], g_w2e_l[D_*D_];
__device__ bf16 g_e2w_h[D_*D_], g_e2w_l[D_*D_];
__device__ bf16 g_e2e_h[D_*D_], g_e2e_l[D_*D_];
__device__ bf16 g_wao_h[D_*D_], g_wao_l[D_*D_];
__device__ bf16 g_wi_h [FF_*D_], g_wi_l [FF_*D_];   // [3072, 768]
__device__ bf16 g_wo_h [D_*FF_], g_wo_l [D_*FF_];   // [768, 3072]

// ---------------- PTX helpers ----------------------------------------------
__device__ __forceinline__ u32 smem_u32(const void* p) {
    u32 a;
    asm("{ .reg .u64 t; cvta.to.shared.u64 t, %1; cvt.u32.u64 %0, t; }" : "=r"(a) : "l"(p));
    return a;
}
__device__ __forceinline__ void cpa16(u32 s, const void* g) {
    asm volatile("cp.async.cg.shared.global [%0], [%1], 16;" :: "r"(s), "l"(g));
}
__device__ __forceinline__ void ldsm4(u32 addr, u32& r0, u32& r1, u32& r2, u32& r3) {
    asm volatile("ldmatrix.sync.aligned.m8n8.x4.shared.b16 {%0,%1,%2,%3}, [%4];"
                 : "=r"(r0), "=r"(r1), "=r"(r2), "=r"(r3) : "r"(addr));
}
__device__ __forceinline__ void mma16816(float* c, const u32* a, u32 b0, u32 b1) {
    asm volatile(
        "mma.sync.aligned.m16n8k16.row.col.f32.bf16.bf16.f32 "
        "{%0,%1,%2,%3}, {%4,%5,%6,%7}, {%8,%9}, {%0,%1,%2,%3};"
        : "+f"(c[0]), "+f"(c[1]), "+f"(c[2]), "+f"(c[3])
        : "r"(a[0]), "r"(a[1]), "r"(a[2]), "r"(a[3]), "r"(b0), "r"(b1));
}

// ---------------- weight transpose + split ----------------------------------
// in: W [K, N] fp32   out: hi/lo [N, K] bf16
__global__ __launch_bounds__(256)
void wconv(const float* __restrict__ W, bf16* __restrict__ th, bf16* __restrict__ tl,
           int K, int N)
{
    __shared__ float t[32][33];
    const int n0 = blockIdx.x * 32, k0 = blockIdx.y * 32;
    const int tx = threadIdx.x & 31, ty = threadIdx.x >> 5;
#pragma unroll
    for (int i = 0; i < 4; i++)
        t[ty + i*8][tx] = W[(size_t)(k0 + ty + i*8) * N + n0 + tx];
    __syncthreads();
#pragma unroll
    for (int i = 0; i < 4; i++) {
        float v = t[tx][ty + i*8];
        bf16 h = __float2bfloat16(v);
        size_t o = (size_t)(n0 + ty + i*8) * K + k0 + tx;
        th[o] = h;
        tl[o] = __float2bfloat16(v - __bfloat162float(h));
    }
}

// ---------------- activation split ------------------------------------------
__global__ __launch_bounds__(256)
void aconv(const float* __restrict__ x, bf16* __restrict__ h, bf16* __restrict__ l)
{
    size_t i = (size_t)blockIdx.x * 256 + threadIdx.x;
    float v = x[i];
    bf16 hi = __float2bfloat16(v);
    h[i] = hi;
    l[i] = __float2bfloat16(v - __bfloat162float(hi));
}

// ---------------- mma.sync split-bf16 GEMM -----------------------------------
// Y[m,n] = A[m,:] @ Bt[n,:] + bias[n]   (A: [M,K] hi/lo, Bt: [N,K] hi/lo)
// Output row remap phys = (m/seg)*T_ + m%seg + rowoff  (seg=M => identity)
// act==0: Y fp32.  act==1: GELU then bf16 split into Yh/Yl.
#define BK_     32
#define LDA_    40                    // padded row stride (bf16 elems) = 80B
#define TILE_BY (128*LDA_*2)          // 10240 B per tile
#define STG_BY  (4*TILE_BY)           // 40960 B per stage
#define SMEM_DYN (2*STG_BY)           // 81920 B

__global__ __launch_bounds__(256, 1)
void gemm_tc(const bf16* __restrict__ Ah, const bf16* __restrict__ Al,
             const bf16* __restrict__ Bh, const bf16* __restrict__ Bl,
             const float* __restrict__ bias,
             float* __restrict__ Y, bf16* __restrict__ Yh, bf16* __restrict__ Yl,
             int M, int N, int K, int seg, int rowoff, int act)
{
    extern __shared__ char smem[];
    const u32 sb = smem_u32(smem);
    const int tid  = threadIdx.x;
    const int lane = tid & 31;
    const int wid  = tid >> 5;
    const int wm   = wid >> 1;     // 0..3
    const int wn   = wid & 1;      // 0..1
    const int n0 = blockIdx.x * 128;
    const int m0 = blockIdx.y * 128;
    const int nk = K / BK_;

    const bf16* srcs[4] = { Ah + (size_t)m0 * K, Al + (size_t)m0 * K,
                            Bh + (size_t)n0 * K, Bl + (size_t)n0 * K };

    // chunk loader: 4 tiles x 128 rows x 32 k (64B data per row, 80B smem row)
    auto load_chunk = [&](int s, int kc) {
        const int k0c = kc * BK_;
#pragma unroll
        for (int i = 0; i < 8; i++) {
            int c   = tid + i * 256;      // 0..2047
            int t   = c >> 9;             // tile 0..3
            int cc  = c & 511;
            int r   = cc >> 2;            // 0..127
            int c16 = cc & 3;             // 16B chunk within row
            cpa16(sb + (u32)s * STG_BY + (u32)t * TILE_BY + (u32)(r * 80 + c16 * 16),
                  srcs[t] + k0c + (size_t)r * K + c16 * 8);
        }
        asm volatile("cp.async.commit_group;" ::: "memory");
    };

    float acc[2][8][4];
#pragma unroll
    for (int mt = 0; mt < 2; mt++)
#pragma unroll
        for (int nt = 0; nt < 8; nt++)
#pragma unroll
            for (int j = 0; j < 4; j++) acc[mt][nt][j] = 0.f;

    // fragment smem address offsets (same pattern for A and B tiles)
    // lanes 0-15: row = base + (lane&15), first 16B; lanes 16-31: +16B
    const u32 frag_row = (u32)(lane & 15);
    const u32 frag_col = (u32)((lane >> 4) << 4);

    load_chunk(0, 0);

    for (int kc = 0; kc < nk; kc++) {
        const int s = kc & 1;
        if (kc + 1 < nk) {
            load_chunk(s ^ 1, kc + 1);
            asm volatile("cp.async.wait_group 1;" ::: "memory");
        } else {
            asm volatile("cp.async.wait_group 0;" ::: "memory");
        }
        __syncthreads();

        const u32 stg = sb + (u32)s * STG_BY;
        const u32 aBaseH = stg + 0 * TILE_BY;
        const u32 aBaseL = stg + 1 * TILE_BY;
        const u32 bBaseH = stg + 2 * TILE_BY;
        const u32 bBaseL = stg + 3 * TILE_BY;

#pragma unroll
        for (int ks = 0; ks < 2; ks++) {
            const u32 kByte = (u32)(ks * 32) + frag_col;
            u32 ah[2][4], al[2][4], bh[4][4], bl[4][4];
#pragma unroll
            for (int mt = 0; mt < 2; mt++) {
                u32 ro = (u32)(wm * 32 + mt * 16) + frag_row;
                ldsm4(aBaseH + ro * 80 + kByte, ah[mt][0], ah[mt][1], ah[mt][2], ah[mt][3]);
                ldsm4(aBaseL + ro * 80 + kByte, al[mt][0], al[mt][1], al[mt][2], al[mt][3]);
            }
#pragma unroll
            for (int np = 0; np < 4; np++) {
                u32 ro = (u32)(wn * 64 + np * 16) + frag_row;
                ldsm4(bBaseH + ro * 80 + kByte, bh[np][0], bh[np][1], bh[np][2], bh[np][3]);
                ldsm4(bBaseL + ro * 80 + kByte, bl[np][0], bl[np][1], bl[np][2], bl[np][3]);
            }
#pragma unroll
            for (int mt = 0; mt < 2; mt++)
#pragma unroll
                for (int nt = 0; nt < 8; nt++) {
                    int np = nt >> 1, sel = nt & 1;
                    u32 b0h = bh[np][sel], b1h = bh[np][sel + 2];
                    u32 b0l = bl[np][sel], b1l = bl[np][sel + 2];
                    mma16816(acc[mt][nt], ah[mt], b0h, b1h);
                    mma16816(acc[mt][nt], ah[mt], b0l, b1l);
                    mma16816(acc[mt][nt], al[mt], b0h, b1h);
                }
        }
        __syncthreads();
    }

    // epilogue
#pragma unroll
    for (int mt = 0; mt < 2; mt++) {
#pragma unroll
        for (int half = 0; half < 2; half++) {   // c0c1 (row) / c2c3 (row+8)
            int mlog = m0 + wm * 32 + mt * 16 + (lane >> 2) + half * 8;
            size_t phys = (size_t)(mlog / seg) * T_ + (mlog % seg) + rowoff;
#pragma unroll
            for (int nt = 0; nt < 8; nt++) {
                int col = n0 + wn * 64 + nt * 8 + (lane & 3) * 2;
                float v0 = acc[mt][nt][half * 2 + 0] + bias[col + 0];
                float v1 = acc[mt][nt][half * 2 + 1] + bias[col + 1];
                if (act == 0) {
                    float2 o = make_float2(v0, v1);
                    *(float2*)(Y + phys * (size_t)N + col) = o;
                } else {
                    v0 = v0 * normcdff(v0);
                    v1 = v1 * normcdff(v1);
                    bf16 h0 = __float2bfloat16(v0), h1 = __float2bfloat16(v1);
                    bf16 l0 = __float2bfloat16(v0 - __bfloat162float(h0));
                    bf16 l1 = __float2bfloat16(v1 - __bfloat162float(h1));
                    *(__nv_bfloat162*)(Yh + phys * (size_t)N + col) = __halves2bfloat162(h0, h1);
                    *(__nv_bfloat162*)(Yl + phys * (size_t)N + col) = __halves2bfloat162(l0, l1);
                }
            }
        }
    }
}

// ---------------- attention (fp32 SIMT) --------------------------------------
__global__ __launch_bounds__(256)
void attn_kernel(const float* __restrict__ q1, const float* __restrict__ q2,
                 const float* __restrict__ k,  const float* __restrict__ v,
                 const float* __restrict__ mask, float* __restrict__ ctx)
{
    __shared__ float sc [8][T_];
    __shared__ float q1s[8][DH_];
    __shared__ float q2s[8][DH_];
    __shared__ float kts[DH_][65];

    const int b  = blockIdx.z;
    const int h  = blockIdx.y;
    const int q0 = blockIdx.x * 8;
    const int tid = threadIdx.x;
    const size_t base = ((size_t)b * T_) * D_ + (size_t)h * DH_;

    for (int f = tid; f < 8 * DH_; f += 256) {
        int qi = f >> 6, d = f & 63;
        q1s[qi][d] = q1[base + (size_t)(q0 + qi) * D_ + d];
        q2s[qi][d] = q2[base + (size_t)(q0 + qi) * D_ + d];
    }

    const int qi   = tid >> 5;
    const int lane = tid & 31;

    for (int kt0 = 0; kt0 < T_; kt0 += 64) {
        __syncthreads();
        for (int f = tid; f < 64 * DH_; f += 256) {
            int tr = f >> 6, d = f & 63;
            kts[d][tr] = k[base + (size_t)(kt0 + tr) * D_ + d];
        }
        __syncthreads();
        const float (*qs)[DH_] = (kt0 < S_) ? q1s : q2s;
        float a0 = 0.f, a1 = 0.f;
#pragma unroll 8
        for (int d = 0; d < DH_; d++) {
            float qv = qs[qi][d];
            a0 += qv * kts[d][lane];
            a1 += qv * kts[d][lane + 32];
        }
        sc[qi][kt0 + lane]      = a0 * 0.125f + mask[b * T_ + kt0 + lane];
        sc[qi][kt0 + lane + 32] = a1 * 0.125f + mask[b * T_ + kt0 + lane + 32];
    }
    __syncthreads();

    {
        const int w = tid >> 5;
        float mx = -3.4e38f;
        for (int t = lane; t < T_; t += 32) mx = fmaxf(mx, sc[w][t]);
#pragma unroll
        for (int o = 16; o; o >>= 1) mx = fmaxf(mx, __shfl_xor_sync(0xffffffffu, mx, o));
        float sum = 0.f;
        for (int t = lane; t < T_; t += 32) {
            float e = expf(sc[w][t] - mx);
            sc[w][t] = e;
            sum += e;
        }
#pragma unroll
        for (int o = 16; o; o >>= 1) sum += __shfl_xor_sync(0xffffffffu, sum, o);
        float inv = 1.f / sum;
        for (int t = lane; t < T_; t += 32) sc[w][t] *= inv;
    }

    float c0 = 0.f, c1 = 0.f;
    for (int vt0 = 0; vt0 < T_; vt0 += 64) {
        __syncthreads();
        for (int f = tid; f < 64 * DH_; f += 256) {
            int tr = f >> 6, d = f & 63;
            kts[tr][d] = v[base + (size_t)(vt0 + tr) * D_ + d];
        }
        __syncthreads();
#pragma unroll 8
        for (int t = 0; t < 64; t++) {
            float p = sc[qi][vt0 + t];
            c0 += p * kts[t][lane];
            c1 += p * kts[t][lane + 32];
        }
    }
    ctx[base + (size_t)(q0 + qi) * D_ + lane]      = c0;
    ctx[base + (size_t)(q0 + qi) * D_ + lane + 32] = c1;
}

// ---------------- residual + LayerNorm (optional bf16-split extra out) -------
__global__ __launch_bounds__(256)
void ln_kernel(const float* __restrict__ raw,
               const float* __restrict__ rw, const float* __restrict__ re,
               const float* __restrict__ rfull, int use_full,
               const float* __restrict__ gm, const float* __restrict__ bt,
               float* __restrict__ out, int final_mode,
               bf16* __restrict__ outH, bf16* __restrict__ outL)
{
    const int row = blockIdx.x;
    const int b = row / T_, t = row % T_;
    const float* rp = use_full
        ? rfull + (size_t)row * D_
        : (t < S_ ? rw + ((size_t)(b * S_ + t)) * D_
                  : re + ((size_t)(b * E_ + t - S_)) * D_);
    const float* x = raw + (size_t)row * D_;

    float vv[3];
    float s = 0.f, sq = 0.f;
#pragma unroll
    for (int i = 0; i < 3; i++) {
        int c = threadIdx.x + i * 256;
        float val = x[c] + rp[c];
        vv[i] = val;
        s += val;
        sq += val * val;
    }
    const int lane = threadIdx.x & 31, w = threadIdx.x >> 5;
#pragma unroll
    for (int o = 16; o; o >>= 1) {
        s  += __shfl_xor_sync(0xffffffffu, s,  o);
        sq += __shfl_xor_sync(0xffffffffu, sq, o);
    }
    __shared__ float ws[8], wq[8];
    __shared__ float sm, sv;
    if (lane == 0) { ws[w] = s; wq[w] = sq; }
    __syncthreads();
    if (threadIdx.x == 0) {
        float ts = 0.f, tq = 0.f;
#pragma unroll
        for (int i = 0; i < 8; i++) { ts += ws[i]; tq += wq[i]; }
        float mean = ts * (1.f / D_);
        sm = mean;
        sv = rsqrtf(tq * (1.f / D_) - mean * mean + 1e-12f);
    }
    __syncthreads();
    const float mean = sm, inv = sv;

    float* o = final_mode
        ? (t < S_ ? out + ((size_t)(b * S_ + t)) * D_
                  : out + (size_t)B_ * S_ * D_ + ((size_t)(b * E_ + t - S_)) * D_)
        : out + (size_t)row * D_;
#pragma unroll
    for (int i = 0; i < 3; i++) {
        int c = threadIdx.x + i * 256;
        float y = (vv[i] - mean) * inv * gm[c] + bt[c];
        o[c] = y;
        if (outH) {
            bf16 h = __float2bfloat16(y);
            outH[(size_t)row * D_ + c] = h;
            outL[(size_t)row * D_ + c] = __float2bfloat16(y - __bfloat162float(h));
        }
    }
}

// ---------------- host -------------------------------------------------------
extern "C" void kernel_launch(void* const* d_in, const int* in_sizes, int n_in,
                              void* d_out, int out_size)
{
    const float* word  = (const float*)d_in[0];
    const float* ent   = (const float*)d_in[1];
    const float* mask  = (const float*)d_in[2];
    const float* W_q   = (const float*)d_in[3],  *b_q    = (const float*)d_in[4];
    const float* W_k   = (const float*)d_in[5],  *b_k    = (const float*)d_in[6];
    const float* W_v   = (const float*)d_in[7],  *b_v    = (const float*)d_in[8];
    const float* W_w2e = (const float*)d_in[9],  *b_w2e  = (const float*)d_in[10];
    const float* W_e2w = (const float*)d_in[11], *b_e2w  = (const float*)d_in[12];
    const float* W_e2e = (const float*)d_in[13], *b_e2e  = (const float*)d_in[14];
    const float* W_ao  = (const float*)d_in[15], *b_ao   = (const float*)d_in[16];
    const float* gm_ao = (const float*)d_in[17], *bt_ao  = (const float*)d_in[18];
    const float* W_i   = (const float*)d_in[19], *b_i    = (const float*)d_in[20];
    const float* W_o   = (const float*)d_in[21], *b_o    = (const float*)d_in[22];
    const float* gm_o  = (const float*)d_in[23], *bt_o   = (const float*)d_in[24];

    void* p;
    cudaGetSymbolAddress(&p, g_q1);     float* d_q1   = (float*)p;
    cudaGetSymbolAddress(&p, g_q2);     float* d_q2   = (float*)p;
    cudaGetSymbolAddress(&p, g_k);      float* d_k    = (float*)p;
    cudaGetSymbolAddress(&p, g_v);      float* d_v    = (float*)p;
    cudaGetSymbolAddress(&p, g_ctx);    float* d_ctx  = (float*)p;
    cudaGetSymbolAddress(&p, g_ao);     float* d_ao   = (float*)p;
    cudaGetSymbolAddress(&p, g_tmp);    float* d_tmp  = (float*)p;

    bf16 *wordH, *wordL, *entH, *entL, *ctxH, *ctxL, *aoH, *aoL, *intH, *intL;
    cudaGetSymbolAddress(&p, g_word_h); wordH = (bf16*)p;
    cudaGetSymbolAddress(&p, g_word_l); wordL = (bf16*)p;
    cudaGetSymbolAddress(&p, g_ent_h);  entH  = (bf16*)p;
    cudaGetSymbolAddress(&p, g_ent_l);  entL  = (bf16*)p;
    cudaGetSymbolAddress(&p, g_ctx_h);  ctxH  = (bf16*)p;
    cudaGetSymbolAddress(&p, g_ctx_l);  ctxL  = (bf16*)p;
    cudaGetSymbolAddress(&p, g_ao_h);   aoH   = (bf16*)p;
    cudaGetSymbolAddress(&p, g_ao_l);   aoL   = (bf16*)p;
    cudaGetSymbolAddress(&p, g_int_h);  intH  = (bf16*)p;
    cudaGetSymbolAddress(&p, g_int_l);  intL  = (bf16*)p;

    bf16 *wqH,*wqL,*wkH,*wkL,*wvH,*wvL,*w2eH,*w2eL,*e2wH,*e2wL,*e2eH,*e2eL,*waoH,*waoL,*wiH,*wiL,*woH,*woL;
    cudaGetSymbolAddress(&p, g_wq_h);  wqH  = (bf16*)p;  cudaGetSymbolAddress(&p, g_wq_l);  wqL  = (bf16*)p;
    cudaGetSymbolAddress(&p, g_wk_h);  wkH  = (bf16*)p;  cudaGetSymbolAddress(&p, g_wk_l);  wkL  = (bf16*)p;
    cudaGetSymbolAddress(&p, g_wv_h);  wvH  = (bf16*)p;  cudaGetSymbolAddress(&p, g_wv_l);  wvL  = (bf16*)p;
    cudaGetSymbolAddress(&p, g_w2e_h); w2eH = (bf16*)p;  cudaGetSymbolAddress(&p, g_w2e_l); w2eL = (bf16*)p;
    cudaGetSymbolAddress(&p, g_e2w_h); e2wH = (bf16*)p;  cudaGetSymbolAddress(&p, g_e2w_l); e2wL = (bf16*)p;
    cudaGetSymbolAddress(&p, g_e2e_h); e2eH = (bf16*)p;  cudaGetSymbolAddress(&p, g_e2e_l); e2eL = (bf16*)p;
    cudaGetSymbolAddress(&p, g_wao_h); waoH = (bf16*)p;  cudaGetSymbolAddress(&p, g_wao_l); waoL = (bf16*)p;
    cudaGetSymbolAddress(&p, g_wi_h);  wiH  = (bf16*)p;  cudaGetSymbolAddress(&p, g_wi_l);  wiL  = (bf16*)p;
    cudaGetSymbolAddress(&p, g_wo_h);  woH  = (bf16*)p;  cudaGetSymbolAddress(&p, g_wo_l);  woL  = (bf16*)p;

    cudaFuncSetAttribute(gemm_tc, cudaFuncAttributeMaxDynamicSharedMemorySize, SMEM_DYN);

    const dim3 thr(256);
    const int MW = B_ * S_;   // 8192
    const int ME = B_ * E_;   // 2048

    // weight transpose+split
    wconv<<<dim3(D_/32,  D_/32),  thr>>>(W_q,   wqH,  wqL,  D_,  D_);
    wconv<<<dim3(D_/32,  D_/32),  thr>>>(W_k,   wkH,  wkL,  D_,  D_);
    wconv<<<dim3(D_/32,  D_/32),  thr>>>(W_v,   wvH,  wvL,  D_,  D_);
    wconv<<<dim3(D_/32,  D_/32),  thr>>>(W_w2e, w2eH, w2eL, D_,  D_);
    wconv<<<dim3(D_/32,  D_/32),  thr>>>(W_e2w, e2wH, e2wL, D_,  D_);
    wconv<<<dim3(D_/32,  D_/32),  thr>>>(W_e2e, e2eH, e2eL, D_,  D_);
    wconv<<<dim3(D_/32,  D_/32),  thr>>>(W_ao,  waoH, waoL, D_,  D_);
    wconv<<<dim3(FF_/32, D_/32),  thr>>>(W_i,   wiH,  wiL,  D_,  FF_);
    wconv<<<dim3(D_/32,  FF_/32), thr>>>(W_o,   woH,  woL,  FF_, D_);

    // activation splits
    aconv<<<(unsigned)((size_t)MW * D_ / 256), thr>>>(word, wordH, wordL);
    aconv<<<(unsigned)((size_t)ME * D_ / 256), thr>>>(ent,  entH,  entL);

    // projections, interleaved into [B,T,D]
    gemm_tc<<<dim3(D_/128, MW/128), thr, SMEM_DYN>>>(wordH, wordL, wqH,  wqL,  b_q,   d_q1, 0,0, MW, D_, D_, S_, 0, 0);
    gemm_tc<<<dim3(D_/128, MW/128), thr, SMEM_DYN>>>(wordH, wordL, w2eH, w2eL, b_w2e, d_q2, 0,0, MW, D_, D_, S_, 0, 0);
    gemm_tc<<<dim3(D_/128, ME/128), thr, SMEM_DYN>>>(entH,  entL,  e2wH, e2wL, b_e2w, d_q1, 0,0, ME, D_, D_, E_, S_, 0);
    gemm_tc<<<dim3(D_/128, ME/128), thr, SMEM_DYN>>>(entH,  entL,  e2eH, e2eL, b_e2e, d_q2, 0,0, ME, D_, D_, E_, S_, 0);
    gemm_tc<<<dim3(D_/128, MW/128), thr, SMEM_DYN>>>(wordH, wordL, wkH,  wkL,  b_k,   d_k,  0,0, MW, D_, D_, S_, 0, 0);
    gemm_tc<<<dim3(D_/128, ME/128), thr, SMEM_DYN>>>(entH,  entL,  wkH,  wkL,  b_k,   d_k,  0,0, ME, D_, D_, E_, S_, 0);
    gemm_tc<<<dim3(D_/128, MW/128), thr, SMEM_DYN>>>(wordH, wordL, wvH,  wvL,  b_v,   d_v,  0,0, MW, D_, D_, S_, 0, 0);
    gemm_tc<<<dim3(D_/128, ME/128), thr, SMEM_DYN>>>(entH,  entL,  wvH,  wvL,  b_v,   d_v,  0,0, ME, D_, D_, E_, S_, 0);

    // attention (fp32 SIMT)
    attn_kernel<<<dim3(T_/8, H_, B_), thr>>>(d_q1, d_q2, d_k, d_v, mask, d_ctx);

    // ctx -> bf16 split, AO projection, LN (emits ao fp32 + bf16 split)
    aconv<<<(unsigned)((size_t)NT_ * D_ / 256), thr>>>(d_ctx, ctxH, ctxL);
    gemm_tc<<<dim3(D_/128, NT_/128), thr, SMEM_DYN>>>(ctxH, ctxL, waoH, waoL, b_ao, d_tmp, 0,0, NT_, D_, D_, NT_, 0, 0);
    ln_kernel<<<NT_, thr>>>(d_tmp, word, ent, d_ao, 0, gm_ao, bt_ao, d_ao, 0, aoH, aoL);

    // FFN1 (+fused GELU, bf16-split out), FFN2
    gemm_tc<<<dim3(FF_/128, NT_/128), thr, SMEM_DYN>>>(aoH, aoL, wiH, wiL, b_i, 0, intH, intL, NT_, FF_, D_, NT_, 0, 1);
    gemm_tc<<<dim3(D_/128, NT_/128), thr, SMEM_DYN>>>(intH, intL, woH, woL, b_o, d_tmp, 0,0, NT_, D_, FF_, NT_, 0, 0);

    // final LN -> split (word, entity) output
    ln_kernel<<<NT_, thr>>>(d_tmp, nullptr, nullptr, d_ao, 1, gm_o, bt_o,
                            (float*)d_out, 1, nullptr, nullptr);
}

// round 5
// speedup vs baseline: 2.5722x; 1.6486x over previous
#include <cuda_runtime.h>
#include <cuda_bf16.h>
#include <stdint.h>
#include <math.h>

// Shapes (fixed for this problem)
#define B_  16
#define S_  512
#define E_  128
#define T_  640      // S_ + E_
#define D_  768
#define H_  12
#define DH_ 64
#define FF_ 3072
#define NT_ (B_*T_) // 10240

typedef __nv_bfloat16 bf16;
typedef unsigned int       u32;
typedef unsigned long long u64;

// ---------------- scratch (__device__ globals) ------------------------------
__device__ float g_ao [(size_t)NT_*D_];
__device__ float g_tmp[(size_t)NT_*D_];

// bf16 split activations
__device__ bf16 g_word_h[(size_t)B_*S_*D_], g_word_l[(size_t)B_*S_*D_];
__device__ bf16 g_ent_h [(size_t)B_*E_*D_], g_ent_l [(size_t)B_*E_*D_];
__device__ bf16 g_q1h[(size_t)NT_*D_], g_q1l[(size_t)NT_*D_];
__device__ bf16 g_q2h[(size_t)NT_*D_], g_q2l[(size_t)NT_*D_];
__device__ bf16 g_kh [(size_t)NT_*D_], g_kl [(size_t)NT_*D_];
__device__ bf16 g_vh [(size_t)NT_*D_], g_vl [(size_t)NT_*D_];
__device__ bf16 g_ctx_h[(size_t)NT_*D_], g_ctx_l[(size_t)NT_*D_];
__device__ bf16 g_ao_h [(size_t)NT_*D_], g_ao_l [(size_t)NT_*D_];
__device__ bf16 g_int_h[(size_t)NT_*FF_], g_int_l[(size_t)NT_*FF_];

// bf16 split transposed weights (stored as [N, K] row-major)
__device__ bf16 g_wq_h [D_*D_], g_wq_l [D_*D_];
__device__ bf16 g_wk_h [D_*D_], g_wk_l [D_*D_];
__device__ bf16 g_wv_h [D_*D_], g_wv_l [D_*D_];
__device__ bf16 g_w2e_h[D_*D_], g_w2e_l[D_*D_];
__device__ bf16 g_e2w_h[D_*D_], g_e2w_l[D_*D_];
__device__ bf16 g_e2e_h[D_*D_], g_e2e_l[D_*D_];
__device__ bf16 g_wao_h[D_*D_], g_wao_l[D_*D_];
__device__ bf16 g_wi_h [FF_*D_], g_wi_l [FF_*D_];
__device__ bf16 g_wo_h [D_*FF_], g_wo_l [D_*FF_];

// ---------------- PTX helpers ----------------------------------------------
__device__ __forceinline__ u32 smem_u32(const void* p) {
    u32 a;
    asm("{ .reg .u64 t; cvta.to.shared.u64 t, %1; cvt.u32.u64 %0, t; }" : "=r"(a) : "l"(p));
    return a;
}
__device__ __forceinline__ void cpa16(u32 s, const void* g) {
    asm volatile("cp.async.cg.shared.global [%0], [%1], 16;" :: "r"(s), "l"(g));
}
__device__ __forceinline__ void ldsm4(u32 addr, u32& r0, u32& r1, u32& r2, u32& r3) {
    asm volatile("ldmatrix.sync.aligned.m8n8.x4.shared.b16 {%0,%1,%2,%3}, [%4];"
                 : "=r"(r0), "=r"(r1), "=r"(r2), "=r"(r3) : "r"(addr));
}
__device__ __forceinline__ void ldsm4t(u32 addr, u32& r0, u32& r1, u32& r2, u32& r3) {
    asm volatile("ldmatrix.sync.aligned.m8n8.x4.trans.shared.b16 {%0,%1,%2,%3}, [%4];"
                 : "=r"(r0), "=r"(r1), "=r"(r2), "=r"(r3) : "r"(addr));
}
__device__ __forceinline__ void mma16816(float* c, const u32* a, u32 b0, u32 b1) {
    asm volatile(
        "mma.sync.aligned.m16n8k16.row.col.f32.bf16.bf16.f32 "
        "{%0,%1,%2,%3}, {%4,%5,%6,%7}, {%8,%9}, {%0,%1,%2,%3};"
        : "+f"(c[0]), "+f"(c[1]), "+f"(c[2]), "+f"(c[3])
        : "r"(a[0]), "r"(a[1]), "r"(a[2]), "r"(a[3]), "r"(b0), "r"(b1));
}
// fast exp via FFMA-only path (rel err ~2.4e-6); valid for x <= ~0
__device__ __forceinline__ float fexp(float x) {
    x = fmaxf(x, -80.f);
    float y = x * 1.4426950408889634f;
    int n = __float2int_rn(y);
    float f = y - (float)n;
    float p = 1.33336e-3f;
    p = fmaf(p, f, 9.61813e-3f);
    p = fmaf(p, f, 5.5504109e-2f);
    p = fmaf(p, f, 2.4022651e-1f);
    p = fmaf(p, f, 6.9314718e-1f);
    p = fmaf(p, f, 1.0f);
    return p * __int_as_float((n + 127) << 23);
}
__device__ __forceinline__ u32 pack_bf2(float a, float b) {
    __nv_bfloat162 t = __floats2bfloat162_rn(a, b);
    return *(u32*)&t;
}
__device__ __forceinline__ float bf_lo(float v) {
    return v - __bfloat162float(__float2bfloat16(v));
}

// ---------------- weight transpose + split ----------------------------------
__global__ __launch_bounds__(256)
void wconv(const float* __restrict__ W, bf16* __restrict__ th, bf16* __restrict__ tl,
           int K, int N)
{
    __shared__ float t[32][33];
    const int n0 = blockIdx.x * 32, k0 = blockIdx.y * 32;
    const int tx = threadIdx.x & 31, ty = threadIdx.x >> 5;
#pragma unroll
    for (int i = 0; i < 4; i++)
        t[ty + i*8][tx] = W[(size_t)(k0 + ty + i*8) * N + n0 + tx];
    __syncthreads();
#pragma unroll
    for (int i = 0; i < 4; i++) {
        float v = t[tx][ty + i*8];
        bf16 h = __float2bfloat16(v);
        size_t o = (size_t)(n0 + ty + i*8) * K + k0 + tx;
        th[o] = h;
        tl[o] = __float2bfloat16(v - __bfloat162float(h));
    }
}

// ---------------- activation split ------------------------------------------
__global__ __launch_bounds__(256)
void aconv(const float* __restrict__ x, bf16* __restrict__ h, bf16* __restrict__ l)
{
    size_t i = (size_t)blockIdx.x * 256 + threadIdx.x;
    float v = x[i];
    bf16 hi = __float2bfloat16(v);
    h[i] = hi;
    l[i] = __float2bfloat16(v - __bfloat162float(hi));
}

// ---------------- mma.sync split-bf16 GEMM -----------------------------------
// act==0: fp32 out. act==1: GELU + bf16 split out. act==2: bias + bf16 split out.
#define BK_     32
#define TILE_BY (128*80)              // 10240 B per tile (80B padded rows)
#define STG_BY  (4*TILE_BY)
#define SMEM_DYN (2*STG_BY)

__global__ __launch_bounds__(256, 1)
void gemm_tc(const bf16* __restrict__ Ah, const bf16* __restrict__ Al,
             const bf16* __restrict__ Bh, const bf16* __restrict__ Bl,
             const float* __restrict__ bias,
             float* __restrict__ Y, bf16* __restrict__ Yh, bf16* __restrict__ Yl,
             int M, int N, int K, int seg, int rowoff, int act)
{
    extern __shared__ char smem[];
    const u32 sb = smem_u32(smem);
    const int tid  = threadIdx.x;
    const int lane = tid & 31;
    const int wid  = tid >> 5;
    const int wm   = wid >> 1;
    const int wn   = wid & 1;
    const int n0 = blockIdx.x * 128;
    const int m0 = blockIdx.y * 128;
    const int nk = K / BK_;

    const bf16* srcs[4] = { Ah + (size_t)m0 * K, Al + (size_t)m0 * K,
                            Bh + (size_t)n0 * K, Bl + (size_t)n0 * K };

    auto load_chunk = [&](int s, int kc) {
        const int k0c = kc * BK_;
#pragma unroll
        for (int i = 0; i < 8; i++) {
            int c   = tid + i * 256;
            int t   = c >> 9;
            int cc  = c & 511;
            int r   = cc >> 2;
            int c16 = cc & 3;
            cpa16(sb + (u32)s * STG_BY + (u32)t * TILE_BY + (u32)(r * 80 + c16 * 16),
                  srcs[t] + k0c + (size_t)r * K + c16 * 8);
        }
        asm volatile("cp.async.commit_group;" ::: "memory");
    };

    float acc[2][8][4];
#pragma unroll
    for (int mt = 0; mt < 2; mt++)
#pragma unroll
        for (int nt = 0; nt < 8; nt++)
#pragma unroll
            for (int j = 0; j < 4; j++) acc[mt][nt][j] = 0.f;

    const u32 frag_row = (u32)(lane & 15);
    const u32 frag_col = (u32)((lane >> 4) << 4);

    load_chunk(0, 0);

    for (int kc = 0; kc < nk; kc++) {
        const int s = kc & 1;
        if (kc + 1 < nk) {
            load_chunk(s ^ 1, kc + 1);
            asm volatile("cp.async.wait_group 1;" ::: "memory");
        } else {
            asm volatile("cp.async.wait_group 0;" ::: "memory");
        }
        __syncthreads();

        const u32 stg = sb + (u32)s * STG_BY;
        const u32 aBaseH = stg + 0 * TILE_BY;
        const u32 aBaseL = stg + 1 * TILE_BY;
        const u32 bBaseH = stg + 2 * TILE_BY;
        const u32 bBaseL = stg + 3 * TILE_BY;

#pragma unroll
        for (int ks = 0; ks < 2; ks++) {
            const u32 kByte = (u32)(ks * 32) + frag_col;
            u32 ah[2][4], al[2][4], bh[4][4], bl[4][4];
#pragma unroll
            for (int mt = 0; mt < 2; mt++) {
                u32 ro = (u32)(wm * 32 + mt * 16) + frag_row;
                ldsm4(aBaseH + ro * 80 + kByte, ah[mt][0], ah[mt][1], ah[mt][2], ah[mt][3]);
                ldsm4(aBaseL + ro * 80 + kByte, al[mt][0], al[mt][1], al[mt][2], al[mt][3]);
            }
#pragma unroll
            for (int np = 0; np < 4; np++) {
                u32 ro = (u32)(wn * 64 + np * 16) + frag_row;
                ldsm4(bBaseH + ro * 80 + kByte, bh[np][0], bh[np][1], bh[np][2], bh[np][3]);
                ldsm4(bBaseL + ro * 80 + kByte, bl[np][0], bl[np][1], bl[np][2], bl[np][3]);
            }
#pragma unroll
            for (int mt = 0; mt < 2; mt++)
#pragma unroll
                for (int nt = 0; nt < 8; nt++) {
                    int np = nt >> 1, sel = nt & 1;
                    u32 b0h = bh[np][sel], b1h = bh[np][sel + 2];
                    u32 b0l = bl[np][sel], b1l = bl[np][sel + 2];
                    mma16816(acc[mt][nt], ah[mt], b0h, b1h);
                    mma16816(acc[mt][nt], ah[mt], b0l, b1l);
                    mma16816(acc[mt][nt], al[mt], b0h, b1h);
                }
        }
        __syncthreads();
    }

#pragma unroll
    for (int mt = 0; mt < 2; mt++) {
#pragma unroll
        for (int half = 0; half < 2; half++) {
            int mlog = m0 + wm * 32 + mt * 16 + (lane >> 2) + half * 8;
            size_t phys = (size_t)(mlog / seg) * T_ + (mlog % seg) + rowoff;
#pragma unroll
            for (int nt = 0; nt < 8; nt++) {
                int col = n0 + wn * 64 + nt * 8 + (lane & 3) * 2;
                float v0 = acc[mt][nt][half * 2 + 0] + bias[col + 0];
                float v1 = acc[mt][nt][half * 2 + 1] + bias[col + 1];
                if (act == 0) {
                    *(float2*)(Y + phys * (size_t)N + col) = make_float2(v0, v1);
                } else {
                    if (act == 1) {
                        v0 = 0.5f * v0 * (1.0f + erff(v0 * 0.70710678f));
                        v1 = 0.5f * v1 * (1.0f + erff(v1 * 0.70710678f));
                    }
                    bf16 h0 = __float2bfloat16(v0), h1 = __float2bfloat16(v1);
                    bf16 l0 = __float2bfloat16(v0 - __bfloat162float(h0));
                    bf16 l1 = __float2bfloat16(v1 - __bfloat162float(h1));
                    *(__nv_bfloat162*)(Yh + phys * (size_t)N + col) = __halves2bfloat162(h0, h1);
                    *(__nv_bfloat162*)(Yl + phys * (size_t)N + col) = __halves2bfloat162(l0, l1);
                }
            }
        }
    }
}

// ---------------- tensor-core flash attention --------------------------------
// 128 queries/block, 5 key tiles of 128 (tiles 0-3: word keys/q1; tile 4: entity keys/q2).
// Padded smem rows: 64 bf16 data + 8 pad = 72 bf16 = 144B (conflict-free ldmatrix).
#define QT_BY   (128*144)            // 18432 B per tile
#define A_Q1H   0
#define A_Q1L   (1*QT_BY)
#define A_Q2H   (2*QT_BY)
#define A_Q2L   (3*QT_BY)
#define A_KH    (4*QT_BY)
#define A_KL    (5*QT_BY)
#define A_VH    (6*QT_BY)
#define A_VL    (7*QT_BY)
#define A_MS    (8*QT_BY)
#define ATT_SMEM (8*QT_BY + 512)     // 147968 B

__global__ __launch_bounds__(256, 1)
void attn_tc(const bf16* __restrict__ q1h, const bf16* __restrict__ q1l,
             const bf16* __restrict__ q2h, const bf16* __restrict__ q2l,
             const bf16* __restrict__ kh,  const bf16* __restrict__ kl,
             const bf16* __restrict__ vh,  const bf16* __restrict__ vl,
             const float* __restrict__ mask,
             bf16* __restrict__ ctxH, bf16* __restrict__ ctxL)
{
    extern __shared__ char smem[];
    const u32 sb = smem_u32(smem);
    float* maskS = (float*)(smem + A_MS);

    const int b  = blockIdx.z;
    const int h  = blockIdx.y;
    const int q0 = blockIdx.x * 128;
    const int tid  = threadIdx.x;
    const int lane = tid & 31;
    const int w    = tid >> 5;

    const u32 frag_row = (u32)(lane & 15);
    const u32 frag_col = (u32)((lane >> 4) << 4);

    // load Q tiles (q1/q2 hi/lo), resident for whole block
    {
        const bf16* srcQ[4] = { q1h, q1l, q2h, q2l };
#pragma unroll
        for (int i = 0; i < 16; i++) {
            int idx = tid + i * 256;            // 0..4095
            int arr = idx >> 10;
            int rr  = (idx >> 3) & 127;
            int ch  = idx & 7;
            cpa16(sb + (u32)(arr * QT_BY + rr * 144 + ch * 16),
                  srcQ[arr] + (size_t)(b * T_ + q0 + rr) * D_ + h * DH_ + ch * 8);
        }
        asm volatile("cp.async.commit_group;" ::: "memory");
    }

    float Oa[8][4];
#pragma unroll
    for (int od = 0; od < 8; od++)
#pragma unroll
        for (int j = 0; j < 4; j++) Oa[od][j] = 0.f;
    float m0 = -1e30f, m1 = -1e30f, l0 = 0.f, l1 = 0.f;

    for (int kt = 0; kt < 5; kt++) {
        __syncthreads();   // previous tile fully consumed
        {
            const bf16* srcT[4] = { kh, kl, vh, vl };
#pragma unroll
            for (int i = 0; i < 16; i++) {
                int idx = tid + i * 256;
                int arr = idx >> 10;
                int rr  = (idx >> 3) & 127;
                int ch  = idx & 7;
                cpa16(sb + (u32)(A_KH + arr * QT_BY + rr * 144 + ch * 16),
                      srcT[arr] + (size_t)(b * T_ + kt * 128 + rr) * D_ + h * DH_ + ch * 8);
            }
            if (tid < 128) maskS[tid] = mask[b * T_ + kt * 128 + tid];
            asm volatile("cp.async.commit_group;" ::: "memory");
            asm volatile("cp.async.wait_group 0;" ::: "memory");
        }
        __syncthreads();

        const u32 qbh = sb + (u32)((kt < 4) ? A_Q1H : A_Q2H);
        const u32 qbl = qbh + QT_BY;

        // ---- scores: S[16q x 128key] per warp ----
        float sc_[16][4];
#pragma unroll
        for (int nt = 0; nt < 16; nt++)
#pragma unroll
            for (int j = 0; j < 4; j++) sc_[nt][j] = 0.f;

#pragma unroll
        for (int ks = 0; ks < 4; ks++) {
            const u32 kByte = (u32)(ks * 32) + frag_col;
            u32 ah[4], al[4], bh[8][4], bl[8][4];
            u32 ro = (u32)(w * 16) + frag_row;
            ldsm4(qbh + ro * 144 + kByte, ah[0], ah[1], ah[2], ah[3]);
            ldsm4(qbl + ro * 144 + kByte, al[0], al[1], al[2], al[3]);
#pragma unroll
            for (int np = 0; np < 8; np++) {
                u32 kr = (u32)(np * 16) + frag_row;
                ldsm4(sb + A_KH + kr * 144 + kByte, bh[np][0], bh[np][1], bh[np][2], bh[np][3]);
                ldsm4(sb + A_KL + kr * 144 + kByte, bl[np][0], bl[np][1], bl[np][2], bl[np][3]);
            }
#pragma unroll
            for (int nt = 0; nt < 16; nt++) {
                int np = nt >> 1, sel = nt & 1;
                u32 b0h = bh[np][sel], b1h = bh[np][sel + 2];
                u32 b0l = bl[np][sel], b1l = bl[np][sel + 2];
                mma16816(sc_[nt], ah, b0h, b1h);
                mma16816(sc_[nt], ah, b0l, b1l);
                mma16816(sc_[nt], al, b0h, b1h);
            }
        }

        // ---- online softmax ----
        float rmax0 = -1e30f, rmax1 = -1e30f;
#pragma unroll
        for (int nt = 0; nt < 16; nt++) {
            int cbase = nt * 8 + (lane & 3) * 2;
            float mk0 = maskS[cbase], mk1 = maskS[cbase + 1];
            sc_[nt][0] = fmaf(sc_[nt][0], 0.125f, mk0);
            sc_[nt][1] = fmaf(sc_[nt][1], 0.125f, mk1);
            sc_[nt][2] = fmaf(sc_[nt][2], 0.125f, mk0);
            sc_[nt][3] = fmaf(sc_[nt][3], 0.125f, mk1);
            rmax0 = fmaxf(rmax0, fmaxf(sc_[nt][0], sc_[nt][1]));
            rmax1 = fmaxf(rmax1, fmaxf(sc_[nt][2], sc_[nt][3]));
        }
        rmax0 = fmaxf(rmax0, __shfl_xor_sync(0xffffffffu, rmax0, 1));
        rmax0 = fmaxf(rmax0, __shfl_xor_sync(0xffffffffu, rmax0, 2));
        rmax1 = fmaxf(rmax1, __shfl_xor_sync(0xffffffffu, rmax1, 1));
        rmax1 = fmaxf(rmax1, __shfl_xor_sync(0xffffffffu, rmax1, 2));

        float mn0 = fmaxf(m0, rmax0), mn1 = fmaxf(m1, rmax1);
        float f0 = fexp(m0 - mn0), f1 = fexp(m1 - mn1);
        float rs0 = 0.f, rs1 = 0.f;
#pragma unroll
        for (int nt = 0; nt < 16; nt++) {
            sc_[nt][0] = fexp(sc_[nt][0] - mn0);
            sc_[nt][1] = fexp(sc_[nt][1] - mn0);
            sc_[nt][2] = fexp(sc_[nt][2] - mn1);
            sc_[nt][3] = fexp(sc_[nt][3] - mn1);
            rs0 += sc_[nt][0] + sc_[nt][1];
            rs1 += sc_[nt][2] + sc_[nt][3];
        }
        rs0 += __shfl_xor_sync(0xffffffffu, rs0, 1);
        rs0 += __shfl_xor_sync(0xffffffffu, rs0, 2);
        rs1 += __shfl_xor_sync(0xffffffffu, rs1, 1);
        rs1 += __shfl_xor_sync(0xffffffffu, rs1, 2);
        l0 = l0 * f0 + rs0;
        l1 = l1 * f1 + rs1;
        m0 = mn0; m1 = mn1;
#pragma unroll
        for (int od = 0; od < 8; od++) {
            Oa[od][0] *= f0; Oa[od][1] *= f0;
            Oa[od][2] *= f1; Oa[od][3] *= f1;
        }

        // ---- P @ V ----
#pragma unroll
        for (int ks2 = 0; ks2 < 8; ks2++) {
            float p00 = sc_[2*ks2][0],   p01 = sc_[2*ks2][1];
            float p02 = sc_[2*ks2][2],   p03 = sc_[2*ks2][3];
            float p10 = sc_[2*ks2+1][0], p11 = sc_[2*ks2+1][1];
            float p12 = sc_[2*ks2+1][2], p13 = sc_[2*ks2+1][3];
            u32 aPh[4], aPl[4];
            aPh[0] = pack_bf2(p00, p01);
            aPh[1] = pack_bf2(p02, p03);
            aPh[2] = pack_bf2(p10, p11);
            aPh[3] = pack_bf2(p12, p13);
            aPl[0] = pack_bf2(bf_lo(p00), bf_lo(p01));
            aPl[1] = pack_bf2(bf_lo(p02), bf_lo(p03));
            aPl[2] = pack_bf2(bf_lo(p10), bf_lo(p11));
            aPl[3] = pack_bf2(bf_lo(p12), bf_lo(p13));

            const u32 vr = (u32)(ks2 * 16) + frag_row;
#pragma unroll
            for (int nd = 0; nd < 4; nd++) {
                const u32 cByte = (u32)(nd * 32) + frag_col;
                u32 vh0, vh1, vh2, vh3, vl0, vl1, vl2, vl3;
                ldsm4t(sb + A_VH + vr * 144 + cByte, vh0, vh1, vh2, vh3);
                ldsm4t(sb + A_VL + vr * 144 + cByte, vl0, vl1, vl2, vl3);
                int od0 = nd * 2, od1 = nd * 2 + 1;
                mma16816(Oa[od0], aPh, vh0, vh1);
                mma16816(Oa[od0], aPh, vl0, vl1);
                mma16816(Oa[od0], aPl, vh0, vh1);
                mma16816(Oa[od1], aPh, vh2, vh3);
                mma16816(Oa[od1], aPh, vl2, vl3);
                mma16816(Oa[od1], aPl, vh2, vh3);
            }
        }
    }

    // ---- epilogue: normalize + split-bf16 write ----
    float inv0 = 1.f / l0, inv1 = 1.f / l1;
    int qa = q0 + w * 16 + (lane >> 2);
    int qb = qa + 8;
    size_t baseA = (size_t)(b * T_ + qa) * D_ + h * DH_;
    size_t baseB = (size_t)(b * T_ + qb) * D_ + h * DH_;
#pragma unroll
    for (int od = 0; od < 8; od++) {
        int col = od * 8 + (lane & 3) * 2;
        float o0 = Oa[od][0] * inv0, o1 = Oa[od][1] * inv0;
        float o2 = Oa[od][2] * inv1, o3 = Oa[od][3] * inv1;
        *(u32*)(ctxH + baseA + col) = pack_bf2(o0, o1);
        *(u32*)(ctxL + baseA + col) = pack_bf2(bf_lo(o0), bf_lo(o1));
        *(u32*)(ctxH + baseB + col) = pack_bf2(o2, o3);
        *(u32*)(ctxL + baseB + col) = pack_bf2(bf_lo(o2), bf_lo(o3));
    }
}

// ---------------- residual + LayerNorm (optional bf16-split extra out) -------
__global__ __launch_bounds__(256)
void ln_kernel(const float* __restrict__ raw,
               const float* __restrict__ rw, const float* __restrict__ re,
               const float* __restrict__ rfull, int use_full,
               const float* __restrict__ gm, const float* __restrict__ bt,
               float* __restrict__ out, int final_mode,
               bf16* __restrict__ outH, bf16* __restrict__ outL)
{
    const int row = blockIdx.x;
    const int b = row / T_, t = row % T_;
    const float* rp = use_full
        ? rfull + (size_t)row * D_
        : (t < S_ ? rw + ((size_t)(b * S_ + t)) * D_
                  : re + ((size_t)(b * E_ + t - S_)) * D_);
    const float* x = raw + (size_t)row * D_;

    float vv[3];
    float s = 0.f, sq = 0.f;
#pragma unroll
    for (int i = 0; i < 3; i++) {
        int c = threadIdx.x + i * 256;
        float val = x[c] + rp[c];
        vv[i] = val;
        s += val;
        sq += val * val;
    }
    const int lane = threadIdx.x & 31, w = threadIdx.x >> 5;
#pragma unroll
    for (int o = 16; o; o >>= 1) {
        s  += __shfl_xor_sync(0xffffffffu, s,  o);
        sq += __shfl_xor_sync(0xffffffffu, sq, o);
    }
    __shared__ float ws[8], wq[8];
    __shared__ float sm, sv;
    if (lane == 0) { ws[w] = s; wq[w] = sq; }
    __syncthreads();
    if (threadIdx.x == 0) {
        float ts = 0.f, tq = 0.f;
#pragma unroll
        for (int i = 0; i < 8; i++) { ts += ws[i]; tq += wq[i]; }
        float mean = ts * (1.f / D_);
        sm = mean;
        sv = rsqrtf(tq * (1.f / D_) - mean * mean + 1e-12f);
    }
    __syncthreads();
    const float mean = sm, inv = sv;

    float* o = final_mode
        ? (t < S_ ? out + ((size_t)(b * S_ + t)) * D_
                  : out + (size_t)B_ * S_ * D_ + ((size_t)(b * E_ + t - S_)) * D_)
        : out + (size_t)row * D_;
#pragma unroll
    for (int i = 0; i < 3; i++) {
        int c = threadIdx.x + i * 256;
        float y = (vv[i] - mean) * inv * gm[c] + bt[c];
        o[c] = y;
        if (outH) {
            bf16 h = __float2bfloat16(y);
            outH[(size_t)row * D_ + c] = h;
            outL[(size_t)row * D_ + c] = __float2bfloat16(y - __bfloat162float(h));
        }
    }
}

// ---------------- host -------------------------------------------------------
extern "C" void kernel_launch(void* const* d_in, const int* in_sizes, int n_in,
                              void* d_out, int out_size)
{
    const float* word  = (const float*)d_in[0];
    const float* ent   = (const float*)d_in[1];
    const float* mask  = (const float*)d_in[2];
    const float* W_q   = (const float*)d_in[3],  *b_q    = (const float*)d_in[4];
    const float* W_k   = (const float*)d_in[5],  *b_k    = (const float*)d_in[6];
    const float* W_v   = (const float*)d_in[7],  *b_v    = (const float*)d_in[8];
    const float* W_w2e = (const float*)d_in[9],  *b_w2e  = (const float*)d_in[10];
    const float* W_e2w = (const float*)d_in[11], *b_e2w  = (const float*)d_in[12];
    const float* W_e2e = (const float*)d_in[13], *b_e2e  = (const float*)d_in[14];
    const float* W_ao  = (const float*)d_in[15], *b_ao   = (const float*)d_in[16];
    const float* gm_ao = (const float*)d_in[17], *bt_ao  = (const float*)d_in[18];
    const float* W_i   = (const float*)d_in[19], *b_i    = (const float*)d_in[20];
    const float* W_o   = (const float*)d_in[21], *b_o    = (const float*)d_in[22];
    const float* gm_o  = (const float*)d_in[23], *bt_o   = (const float*)d_in[24];

    void* p;
    cudaGetSymbolAddress(&p, g_ao);    float* d_ao  = (float*)p;
    cudaGetSymbolAddress(&p, g_tmp);   float* d_tmp = (float*)p;

    bf16 *wordH,*wordL,*entH,*entL,*q1H,*q1L,*q2H,*q2L,*kH,*kL,*vH,*vL,*ctxH,*ctxL,*aoH,*aoL,*intH,*intL;
    cudaGetSymbolAddress(&p, g_word_h); wordH = (bf16*)p;
    cudaGetSymbolAddress(&p, g_word_l); wordL = (bf16*)p;
    cudaGetSymbolAddress(&p, g_ent_h);  entH  = (bf16*)p;
    cudaGetSymbolAddress(&p, g_ent_l);  entL  = (bf16*)p;
    cudaGetSymbolAddress(&p, g_q1h);    q1H   = (bf16*)p;
    cudaGetSymbolAddress(&p, g_q1l);    q1L   = (bf16*)p;
    cudaGetSymbolAddress(&p, g_q2h);    q2H   = (bf16*)p;
    cudaGetSymbolAddress(&p, g_q2l);    q2L   = (bf16*)p;
    cudaGetSymbolAddress(&p, g_kh);     kH    = (bf16*)p;
    cudaGetSymbolAddress(&p, g_kl);     kL    = (bf16*)p;
    cudaGetSymbolAddress(&p, g_vh);     vH    = (bf16*)p;
    cudaGetSymbolAddress(&p, g_vl);     vL    = (bf16*)p;
    cudaGetSymbolAddress(&p, g_ctx_h);  ctxH  = (bf16*)p;
    cudaGetSymbolAddress(&p, g_ctx_l);  ctxL  = (bf16*)p;
    cudaGetSymbolAddress(&p, g_ao_h);   aoH   = (bf16*)p;
    cudaGetSymbolAddress(&p, g_ao_l);   aoL   = (bf16*)p;
    cudaGetSymbolAddress(&p, g_int_h);  intH  = (bf16*)p;
    cudaGetSymbolAddress(&p, g_int_l);  intL  = (bf16*)p;

    bf16 *wqH,*wqL,*wkH,*wkL,*wvH,*wvL,*w2eH,*w2eL,*e2wH,*e2wL,*e2eH,*e2eL,*waoH,*waoL,*wiH,*wiL,*woH,*woL;
    cudaGetSymbolAddress(&p, g_wq_h);  wqH  = (bf16*)p;  cudaGetSymbolAddress(&p, g_wq_l);  wqL  = (bf16*)p;
    cudaGetSymbolAddress(&p, g_wk_h);  wkH  = (bf16*)p;  cudaGetSymbolAddress(&p, g_wk_l);  wkL  = (bf16*)p;
    cudaGetSymbolAddress(&p, g_wv_h);  wvH  = (bf16*)p;  cudaGetSymbolAddress(&p, g_wv_l);  wvL  = (bf16*)p;
    cudaGetSymbolAddress(&p, g_w2e_h); w2eH = (bf16*)p;  cudaGetSymbolAddress(&p, g_w2e_l); w2eL = (bf16*)p;
    cudaGetSymbolAddress(&p, g_e2w_h); e2wH = (bf16*)p;  cudaGetSymbolAddress(&p, g_e2w_l); e2wL = (bf16*)p;
    cudaGetSymbolAddress(&p, g_e2e_h); e2eH = (bf16*)p;  cudaGetSymbolAddress(&p, g_e2e_l); e2eL = (bf16*)p;
    cudaGetSymbolAddress(&p, g_wao_h); waoH = (bf16*)p;  cudaGetSymbolAddress(&p, g_wao_l); waoL = (bf16*)p;
    cudaGetSymbolAddress(&p, g_wi_h);  wiH  = (bf16*)p;  cudaGetSymbolAddress(&p, g_wi_l);  wiL  = (bf16*)p;
    cudaGetSymbolAddress(&p, g_wo_h);  woH  = (bf16*)p;  cudaGetSymbolAddress(&p, g_wo_l);  woL  = (bf16*)p;

    cudaFuncSetAttribute(gemm_tc, cudaFuncAttributeMaxDynamicSharedMemorySize, SMEM_DYN);
    cudaFuncSetAttribute(attn_tc, cudaFuncAttributeMaxDynamicSharedMemorySize, ATT_SMEM);

    const dim3 thr(256);
    const int MW = B_ * S_;
    const int ME = B_ * E_;

    wconv<<<dim3(D_/32,  D_/32),  thr>>>(W_q,   wqH,  wqL,  D_,  D_);
    wconv<<<dim3(D_/32,  D_/32),  thr>>>(W_k,   wkH,  wkL,  D_,  D_);
    wconv<<<dim3(D_/32,  D_/32),  thr>>>(W_v,   wvH,  wvL,  D_,  D_);
    wconv<<<dim3(D_/32,  D_/32),  thr>>>(W_w2e, w2eH, w2eL, D_,  D_);
    wconv<<<dim3(D_/32,  D_/32),  thr>>>(W_e2w, e2wH, e2wL, D_,  D_);
    wconv<<<dim3(D_/32,  D_/32),  thr>>>(W_e2e, e2eH, e2eL, D_,  D_);
    wconv<<<dim3(D_/32,  D_/32),  thr>>>(W_ao,  waoH, waoL, D_,  D_);
    wconv<<<dim3(FF_/32, D_/32),  thr>>>(W_i,   wiH,  wiL,  D_,  FF_);
    wconv<<<dim3(D_/32,  FF_/32), thr>>>(W_o,   woH,  woL,  FF_, D_);

    aconv<<<(unsigned)((size_t)MW * D_ / 256), thr>>>(word, wordH, wordL);
    aconv<<<(unsigned)((size_t)ME * D_ / 256), thr>>>(ent,  entH,  entL);

    // projections -> bf16 split, interleaved into [B,T,D]
    gemm_tc<<<dim3(D_/128, MW/128), thr, SMEM_DYN>>>(wordH, wordL, wqH,  wqL,  b_q,   0, q1H, q1L, MW, D_, D_, S_, 0, 2);
    gemm_tc<<<dim3(D_/128, MW/128), thr, SMEM_DYN>>>(wordH, wordL, w2eH, w2eL, b_w2e, 0, q2H, q2L, MW, D_, D_, S_, 0, 2);
    gemm_tc<<<dim3(D_/128, ME/128), thr, SMEM_DYN>>>(entH,  entL,  e2wH, e2wL, b_e2w, 0, q1H, q1L, ME, D_, D_, E_, S_, 2);
    gemm_tc<<<dim3(D_/128, ME/128), thr, SMEM_DYN>>>(entH,  entL,  e2eH, e2eL, b_e2e, 0, q2H, q2L, ME, D_, D_, E_, S_, 2);
    gemm_tc<<<dim3(D_/128, MW/128), thr, SMEM_DYN>>>(wordH, wordL, wkH,  wkL,  b_k,   0, kH,  kL,  MW, D_, D_, S_, 0, 2);
    gemm_tc<<<dim3(D_/128, ME/128), thr, SMEM_DYN>>>(entH,  entL,  wkH,  wkL,  b_k,   0, kH,  kL,  ME, D_, D_, E_, S_, 2);
    gemm_tc<<<dim3(D_/128, MW/128), thr, SMEM_DYN>>>(wordH, wordL, wvH,  wvL,  b_v,   0, vH,  vL,  MW, D_, D_, S_, 0, 2);
    gemm_tc<<<dim3(D_/128, ME/128), thr, SMEM_DYN>>>(entH,  entL,  wvH,  wvL,  b_v,   0, vH,  vL,  ME, D_, D_, E_, S_, 2);

    // tensor-core attention -> split ctx
    attn_tc<<<dim3(T_/128, H_, B_), thr, ATT_SMEM>>>(q1H, q1L, q2H, q2L, kH, kL, vH, vL,
                                                     mask, ctxH, ctxL);

    // AO projection + LN
    gemm_tc<<<dim3(D_/128, NT_/128), thr, SMEM_DYN>>>(ctxH, ctxL, waoH, waoL, b_ao, d_tmp, 0, 0, NT_, D_, D_, NT_, 0, 0);
    ln_kernel<<<NT_, thr>>>(d_tmp, word, ent, d_ao, 0, gm_ao, bt_ao, d_ao, 0, aoH, aoL);

    // FFN
    gemm_tc<<<dim3(FF_/128, NT_/128), thr, SMEM_DYN>>>(aoH, aoL, wiH, wiL, b_i, 0, intH, intL, NT_, FF_, D_, NT_, 0, 1);
    gemm_tc<<<dim3(D_/128, NT_/128), thr, SMEM_DYN>>>(intH, intL, woH, woL, b_o, d_tmp, 0, 0, NT_, D_, FF_, NT_, 0, 0);

    // final LN -> split (word, entity) output
    ln_kernel<<<NT_, thr>>>(d_tmp, nullptr, nullptr, d_ao, 1, gm_o, bt_o,
                            (float*)d_out, 1, nullptr, nullptr);
}